// round 4
// baseline (speedup 1.0000x reference)
#include <cuda_runtime.h>
#include <math.h>

#define B_    16
#define C_    512
#define HW_   4096
#define CM_   32      // C // R
#define CI_   64      // C // 8
#define EPSF  1e-5f
#define INV_HW (1.0f/4096.0f)

// ---------------- device scratch (no allocations allowed) ----------------
__device__ float g_h1[B_*CM_*HW_];   // conv1 output  [b][k][p]
__device__ float g_ap[B_*C_];        // spatial sums of x
__device__ float g_sum[B_*C_];       // sum of relu(y2)
__device__ float g_ssq[B_*C_];       // sum of relu(y2)^2
__device__ float g_red[B_];          // sum over c of m
__device__ float g_sm[B_];           // final softmax scalars

// ---------------- K0: zero accumulators ----------------
__global__ void k_zero() {
    int i = blockIdx.x * blockDim.x + threadIdx.x;
    if (i < B_*C_) { g_ap[i] = 0.f; g_sum[i] = 0.f; g_ssq[i] = 0.f; }
}

// ---------------- K1: conv1x1 (512->32) + spatial sums of x ----------------
// grid (16 pixel tiles of 256, 16 b), 256 threads.
// Per-thread: 4 k-channels x 8 pixels. Register-staged double buffering,
// swizzled conflict-free STS, [k][c] weight layout (broadcast LDS).
__global__ __launch_bounds__(256) void k_conv1(const float* __restrict__ x,
                                               const float* __restrict__ w1,
                                               const float* __restrict__ b1) {
    __shared__ float xs[32*256];    // [c_local][p]  32KB
    __shared__ float ws2[32*32];    // [k][c_local]  4KB
    __shared__ float aps[512];

    const int tid = threadIdx.x;
    const int b   = blockIdx.y;
    const int p0  = blockIdx.x << 8;

    const int tk = tid >> 5;        // warp id 0..7 -> k0 = tk*4
    const int tp = tid & 31;        // pixel group: pA = tp*4, pB = 128 + tp*4
    const int lrow = tid >> 3;      // staging channel row 0..31
    const int cw   = tid & 7;       // staging col group 0..7
    const int kw = tid >> 3;        // w-load: k row 0..31
    const int cq = tid & 7;         // w-load: 4-float col group

    aps[tid] = 0.f; aps[tid + 256] = 0.f;
    __syncthreads();

    float acc[4][8];
#pragma unroll
    for (int i = 0; i < 4; i++)
#pragma unroll
        for (int j = 0; j < 8; j++) acc[i][j] = 0.f;

    const float* xbase = x + (size_t)(b*C_ + lrow) * HW_ + p0 + (cw << 5);

    float4 xst[8];
    float4 wst;
#pragma unroll
    for (int u = 0; u < 8; u++) xst[u] = *(const float4*)(xbase + (u << 2));
    wst = *(const float4*)(w1 + kw*C_ + (cq << 2));
    {
        float part = 0.f;
#pragma unroll
        for (int u = 0; u < 8; u++)
            part += xst[u].x + xst[u].y + xst[u].z + xst[u].w;
        atomicAdd(&aps[lrow], part);
    }

    for (int cc = 0; cc < 512; cc += 32) {
        __syncthreads();
#pragma unroll
        for (int j = 0; j < 8; j++) {
            int u = (j + cw) & 7;
            *(float4*)&xs[(lrow << 8) + (((cw << 3) + u) << 2)] = xst[u];
        }
        *(float4*)&ws2[(kw << 5) + (cq << 2)] = wst;
        __syncthreads();

        if (cc + 32 < 512) {
            const float* xn = xbase + (size_t)(cc + 32) * HW_;
#pragma unroll
            for (int u = 0; u < 8; u++) xst[u] = *(const float4*)(xn + (u << 2));
            wst = *(const float4*)(w1 + kw*C_ + cc + 32 + (cq << 2));
            float part = 0.f;
#pragma unroll
            for (int u = 0; u < 8; u++)
                part += xst[u].x + xst[u].y + xst[u].z + xst[u].w;
            atomicAdd(&aps[cc + 32 + lrow], part);
        }

#pragma unroll
        for (int cl = 0; cl < 32; cl++) {
            float4 xa = *(const float4*)&xs[(cl << 8) + (tp << 2)];
            float4 xb = *(const float4*)&xs[(cl << 8) + 128 + (tp << 2)];
#pragma unroll
            for (int i = 0; i < 4; i++) {
                float wv = ws2[(((tk << 2) + i) << 5) + cl];   // broadcast
                acc[i][0] = fmaf(wv, xa.x, acc[i][0]);
                acc[i][1] = fmaf(wv, xa.y, acc[i][1]);
                acc[i][2] = fmaf(wv, xa.z, acc[i][2]);
                acc[i][3] = fmaf(wv, xa.w, acc[i][3]);
                acc[i][4] = fmaf(wv, xb.x, acc[i][4]);
                acc[i][5] = fmaf(wv, xb.y, acc[i][5]);
                acc[i][6] = fmaf(wv, xb.z, acc[i][6]);
                acc[i][7] = fmaf(wv, xb.w, acc[i][7]);
            }
        }
    }

#pragma unroll
    for (int i = 0; i < 4; i++) {
        int k = (tk << 2) + i;
        float bias = __ldg(&b1[k]);
        float4 oA = make_float4(acc[i][0]+bias, acc[i][1]+bias,
                                acc[i][2]+bias, acc[i][3]+bias);
        float4 oB = make_float4(acc[i][4]+bias, acc[i][5]+bias,
                                acc[i][6]+bias, acc[i][7]+bias);
        *(float4*)&g_h1[(size_t)(b*CM_ + k) * HW_ + p0 + (tp << 2)]       = oA;
        *(float4*)&g_h1[(size_t)(b*CM_ + k) * HW_ + p0 + 128 + (tp << 2)] = oB;
    }
    __syncthreads();
    for (int i = tid; i < 512; i += 256) atomicAdd(&g_ap[b*C_ + i], aps[i]);
}

// ---------------- K2: FUSED 3x3 conv (32->32) + 1x1 conv (32->512) + stats --
// grid (16 tiles of 16x16, 16 b), 512 threads.
// Phase 1: conv3 into registers (thread = (co-half, pixel), 16 accs).
// Phase 2: h3 tile lives in smem; thread = out-channel c, W2 row in regs,
//          ReLU + sum/sumsq accumulated, atomically added to global stats.
__global__ __launch_bounds__(512) void k_conv32(const float* __restrict__ w3,
                                                const float* __restrict__ b3,
                                                const float* __restrict__ w2,
                                                const float* __restrict__ b2) {
    extern __shared__ float sm3[];
    float* w3s = sm3;            // 9216: [(ci*9+q)*32 + co]
    float* ins = sm3 + 9216;     // phase1: 32*18*18 = 10368 ; phase2: h3 [256][36]

    const int tid = threadIdx.x;
    const int b = blockIdx.y, tile = blockIdx.x;
    const int ty0 = (tile >> 2) << 4, tx0 = (tile & 3) << 4;

    for (int i = tid; i < 9216; i += 512) {
        int co = i & 31, r = i >> 5;            // r = ci*9+q
        w3s[i] = w3[co * 288 + r];
    }
    for (int i = tid; i < 10368; i += 512) {
        int ci = i / 324; int rem = i - ci*324;
        int yy = rem / 18; int xx = rem - yy*18;
        int gy = ty0 - 1 + yy, gx = tx0 - 1 + xx;
        float v = 0.f;
        if ((unsigned)gy < 64u && (unsigned)gx < 64u)
            v = g_h1[((b*CM_ + ci) << 12) + (gy << 6) + gx];
        ins[i] = v;
    }
    __syncthreads();

    // ---- phase 1: 3x3 conv ----
    const int half = tid >> 8;           // 0/1 -> co base = half*16
    const int px = tid & 255;
    const int py = px >> 4, pxx = px & 15;

    float acc[16];
#pragma unroll
    for (int i = 0; i < 16; i++) acc[i] = 0.f;

    for (int ci = 0; ci < 32; ci++) {
        const float* ib = &ins[ci*324 + py*18 + pxx];
#pragma unroll
        for (int q = 0; q < 9; q++) {
            float v = ib[(q/3)*18 + (q%3)];
            const float4* wr = (const float4*)&w3s[((ci*9 + q) << 5) + (half << 4)];
#pragma unroll
            for (int g = 0; g < 4; g++) {
                float4 wv = wr[g];
                acc[g*4+0] = fmaf(wv.x, v, acc[g*4+0]);
                acc[g*4+1] = fmaf(wv.y, v, acc[g*4+1]);
                acc[g*4+2] = fmaf(wv.z, v, acc[g*4+2]);
                acc[g*4+3] = fmaf(wv.w, v, acc[g*4+3]);
            }
        }
    }
    __syncthreads();   // everyone done reading ins before reuse

    // store h3 tile: [p][k], stride 36 (float4-aligned)
#pragma unroll
    for (int g = 0; g < 4; g++) {
        float4 o = make_float4(acc[g*4+0] + __ldg(&b3[(half<<4)+g*4+0]),
                               acc[g*4+1] + __ldg(&b3[(half<<4)+g*4+1]),
                               acc[g*4+2] + __ldg(&b3[(half<<4)+g*4+2]),
                               acc[g*4+3] + __ldg(&b3[(half<<4)+g*4+3]));
        *(float4*)&ins[px*36 + (half << 4) + (g << 2)] = o;
    }
    __syncthreads();

    // ---- phase 2: 1x1 conv 32->512 + ReLU + stats ----
    const int c = tid;
    float wr2[32];
#pragma unroll
    for (int g = 0; g < 8; g++)
        *(float4*)&wr2[g*4] = *(const float4*)&w2[(c << 5) + (g << 2)];
    const float bias = __ldg(&b2[c]);

    float s = 0.f, q = 0.f;
#pragma unroll 2
    for (int p = 0; p < 256; p++) {
        const float* row = &ins[p*36];
        float y0 = bias, y1 = 0.f;
#pragma unroll
        for (int g = 0; g < 8; g += 2) {
            float4 h0 = *(const float4*)(row + (g << 2));
            float4 h1 = *(const float4*)(row + ((g+1) << 2));
            y0 = fmaf(wr2[g*4+0], h0.x, y0); y0 = fmaf(wr2[g*4+1], h0.y, y0);
            y0 = fmaf(wr2[g*4+2], h0.z, y0); y0 = fmaf(wr2[g*4+3], h0.w, y0);
            y1 = fmaf(wr2[g*4+4], h1.x, y1); y1 = fmaf(wr2[g*4+5], h1.y, y1);
            y1 = fmaf(wr2[g*4+6], h1.z, y1); y1 = fmaf(wr2[g*4+7], h1.w, y1);
        }
        float y = fmaxf(y0 + y1, 0.f);
        s += y; q = fmaf(y, y, q);
    }
    atomicAdd(&g_sum[b*C_ + c], s);
    atomicAdd(&g_ssq[b*C_ + c], q);
}

// ---------------- K3: combine (ggt1 folded in) -> Sum_c m[b][c] ----------------
// grid 16 (b), 512 threads (c).
__global__ __launch_bounds__(512) void k_combine(const float* __restrict__ w0,
                                                 const float* __restrict__ b0,
                                                 const float* __restrict__ gw,
                                                 const float* __restrict__ aw1,
                                                 const float* __restrict__ ab1,
                                                 const float* __restrict__ ag,
                                                 const float* __restrict__ abeta,
                                                 const float* __restrict__ lg,
                                                 const float* __restrict__ lb,
                                                 const float* __restrict__ maskw) {
    __shared__ float t1s[B_*CM_];
    __shared__ float ggs[CI_];
    __shared__ float red;
    const int tid = threadIdx.x, b = blockIdx.x, c = tid;

    // t1[bp][j] = (ap[bp] . w0[j]) * INV_HW + b0[j]   (recomputed per block)
    {
        int bp = tid >> 5, j = tid & 31;
        const float* ar = g_ap + bp*C_;
        const float* wr = w0 + j*C_;
        float v = 0.f;
#pragma unroll 4
        for (int k = 0; k < 512; k += 4) {
            v = fmaf(__ldg(&ar[k+0]), __ldg(&wr[k+0]), v);
            v = fmaf(__ldg(&ar[k+1]), __ldg(&wr[k+1]), v);
            v = fmaf(__ldg(&ar[k+2]), __ldg(&wr[k+2]), v);
            v = fmaf(__ldg(&ar[k+3]), __ldg(&wr[k+3]), v);
        }
        t1s[tid] = v * INV_HW + __ldg(&b0[j]);
    }
    // gg[ci] for own b
    if (tid < CI_) {
        const float* ar = g_ap + b*C_;
        const float* wr = gw + tid*C_;
        float v = 0.f;
#pragma unroll 4
        for (int k = 0; k < 512; k += 4) {
            v = fmaf(__ldg(&ar[k+0]), __ldg(&wr[k+0]), v);
            v = fmaf(__ldg(&ar[k+1]), __ldg(&wr[k+1]), v);
            v = fmaf(__ldg(&ar[k+2]), __ldg(&wr[k+2]), v);
            v = fmaf(__ldg(&ar[k+3]), __ldg(&wr[k+3]), v);
        }
        ggs[tid] = v * INV_HW;
    }
    if (tid == 0) red = 0.f;
    __syncthreads();

    float wr[32];
#pragma unroll
    for (int g = 0; g < 8; g++)
        *(float4*)&wr[g*4] = *(const float4*)&aw1[(c << 5) + (g << 2)];
    const float bb = __ldg(&ab1[c]);

    // ac branch: t2 for all b', BN over batch, pick own b
    float mu = 0.f, e2 = 0.f, vown = 0.f;
#pragma unroll
    for (int bp = 0; bp < 16; bp++) {
        float v = bb;
#pragma unroll
        for (int j = 0; j < 32; j++) v = fmaf(t1s[(bp << 5) + j], wr[j], v);
        mu += v; e2 = fmaf(v, v, e2);
        if (bp == b) vown = v;
    }
    mu *= (1.f/16.f); e2 *= (1.f/16.f);
    float var = e2 - mu*mu;
    float acv = fmaxf((vown - mu) * rsqrtf(var + EPSF) * __ldg(&ag[c]) + __ldg(&abeta[c]), 0.f);

    // als branch from stats
    float ssum = 0.f, sssq = 0.f, sb = 0.f;
#pragma unroll
    for (int bp = 0; bp < 16; bp++) {
        float s = g_sum[(bp << 9) + c];
        ssum += s; sssq += g_ssq[(bp << 9) + c];
        if (bp == b) sb = s;
    }
    float muA  = ssum * (INV_HW / 16.f);
    float e2A  = sssq * (INV_HW / 16.f);
    float varA = e2A - muA*muA;
    float gals = (sb * INV_HW - muA) * rsqrtf(varA + EPSF) * __ldg(&lg[c]) + __ldg(&lb[c]);

    // ags branch (attention collapsed): mask_w @ gg + ap_mean
    float gacc = g_ap[(b << 9) + c] * INV_HW;
    const float* mr = maskw + (c << 6);
#pragma unroll
    for (int qd = 0; qd < 16; qd++) {
        float4 mv = *(const float4*)&mr[qd << 2];
        gacc = fmaf(mv.x, ggs[qd*4+0], gacc);
        gacc = fmaf(mv.y, ggs[qd*4+1], gacc);
        gacc = fmaf(mv.z, ggs[qd*4+2], gacc);
        gacc = fmaf(mv.w, ggs[qd*4+3], gacc);
    }

    float m = fmaxf(fmaxf(acv, gals), gacc);
#pragma unroll
    for (int o = 16; o; o >>= 1) m += __shfl_xor_sync(0xffffffffu, m, o);
    if ((tid & 31) == 0) atomicAdd(&red, m);
    __syncthreads();
    if (tid == 0) g_red[b] = red;
}

// ---------------- K4: softmax over batch ----------------
__global__ void k_softmax() {
    int lane = threadIdx.x;
    float v = (lane < 16) ? g_red[lane] * (1.f/512.f) : -1e30f;
    float mx = v;
#pragma unroll
    for (int o = 16; o; o >>= 1) mx = fmaxf(mx, __shfl_xor_sync(0xffffffffu, mx, o));
    float e = (lane < 16) ? expf(v - mx) : 0.f;
    float s = e;
#pragma unroll
    for (int o = 16; o; o >>= 1) s += __shfl_xor_sync(0xffffffffu, s, o);
    if (lane < 16) g_sm[lane] = e / s;
}

// ---------------- K5: out = sm[b] * x ----------------
__global__ __launch_bounds__(256) void k_scale(const float4* __restrict__ x,
                                               float4* __restrict__ out) {
    __shared__ float sms[16];
    if (threadIdx.x < 16) sms[threadIdx.x] = g_sm[threadIdx.x];
    __syncthreads();
    const int n4 = B_*C_*HW_/4;   // 8388608
    for (int i = blockIdx.x * blockDim.x + threadIdx.x; i < n4;
         i += gridDim.x * blockDim.x) {
        float s = sms[i >> 19];
        float4 v = x[i];
        out[i] = make_float4(v.x*s, v.y*s, v.z*s, v.w*s);
    }
}

// ---------------- launch ----------------
extern "C" void kernel_launch(void* const* d_in, const int* in_sizes, int n_in,
                              void* d_out, int out_size) {
    const float* x        = (const float*)d_in[0];
    const float* ac_w0    = (const float*)d_in[1];
    const float* ac_b0    = (const float*)d_in[2];
    const float* ac_w1    = (const float*)d_in[3];
    const float* ac_b1    = (const float*)d_in[4];
    const float* ac_gamma = (const float*)d_in[5];
    const float* ac_beta  = (const float*)d_in[6];
    const float* als_w1   = (const float*)d_in[7];
    const float* als_b1   = (const float*)d_in[8];
    const float* als_w3   = (const float*)d_in[9];
    const float* als_b3   = (const float*)d_in[10];
    const float* als_w2   = (const float*)d_in[11];
    const float* als_b2   = (const float*)d_in[12];
    const float* als_gamma= (const float*)d_in[13];
    const float* als_beta = (const float*)d_in[14];
    // d_in[15] = phi_w, d_in[16] = theta_w : provably unused (softmax col sums = 1)
    const float* g_w      = (const float*)d_in[17];
    const float* mask_w   = (const float*)d_in[18];
    float* out = (float*)d_out;

    const int SMEM32 = (9216 + 10368) * 4;   // 78336 B
    cudaFuncSetAttribute(k_conv32, cudaFuncAttributeMaxDynamicSharedMemorySize, SMEM32);

    k_zero<<<16, 512>>>();
    k_conv1<<<dim3(16, 16), 256>>>(x, als_w1, als_b1);
    k_conv32<<<dim3(16, 16), 512, SMEM32>>>(als_w3, als_b3, als_w2, als_b2);
    k_combine<<<16, 512>>>(ac_w0, ac_b0, g_w, ac_w1, ac_b1, ac_gamma, ac_beta,
                           als_gamma, als_beta, mask_w);
    k_softmax<<<1, 32>>>();
    k_scale<<<4736, 256>>>((const float4*)x, (float4*)out);
}

// round 5
// speedup vs baseline: 1.4817x; 1.4817x over previous
#include <cuda_runtime.h>
#include <math.h>

#define B_    16
#define C_    512
#define HW_   4096
#define CM_   32      // C // R
#define CI_   64      // C // 8
#define EPSF  1e-5f
#define INV_HW (1.0f/4096.0f)

// ---------------- device scratch (no allocations allowed) ----------------
__device__ float g_h1[B_*CM_*HW_];   // conv1 output  [b][k][p]
__device__ float g_ap[B_*C_];        // spatial sums of x
__device__ float g_sum[B_*C_];       // sum of relu(y2)
__device__ float g_ssq[B_*C_];       // sum of relu(y2)^2
__device__ float g_gg[B_*CI_];       // g_w @ ap (means)
__device__ float g_t1[B_*CM_];       // ac first layer
__device__ float g_red[B_];          // sum over c of m
__device__ float g_sm[B_];           // final softmax scalars

// ---------------- K0: zero accumulators ----------------
__global__ void k_zero() {
    int i = blockIdx.x * blockDim.x + threadIdx.x;
    if (i < B_*C_) { g_ap[i] = 0.f; g_sum[i] = 0.f; g_ssq[i] = 0.f; }
}

// ---------------- K1: conv1x1 (512->32) + spatial sums of x ----------------
// grid (16 pixel tiles of 256, 16 b), 256 threads.
// Per-thread: 4 k-channels x 8 pixels. Register-staged double buffering,
// swizzled conflict-free STS, [k][c] weight layout (broadcast LDS).
__global__ __launch_bounds__(256) void k_conv1(const float* __restrict__ x,
                                               const float* __restrict__ w1,
                                               const float* __restrict__ b1) {
    __shared__ float xs[32*256];    // [c_local][p]  32KB
    __shared__ float ws2[32*32];    // [k][c_local]  4KB
    __shared__ float aps[512];

    const int tid = threadIdx.x;
    const int b   = blockIdx.y;
    const int p0  = blockIdx.x << 8;

    const int tk = tid >> 5;        // warp id 0..7 -> k0 = tk*4
    const int tp = tid & 31;        // pixel group: pA = tp*4, pB = 128 + tp*4
    const int lrow = tid >> 3;      // staging channel row 0..31
    const int cw   = tid & 7;       // staging col group 0..7
    const int kw = tid >> 3;        // w-load: k row 0..31
    const int cq = tid & 7;         // w-load: 4-float col group

    aps[tid] = 0.f; aps[tid + 256] = 0.f;
    __syncthreads();

    float acc[4][8];
#pragma unroll
    for (int i = 0; i < 4; i++)
#pragma unroll
        for (int j = 0; j < 8; j++) acc[i][j] = 0.f;

    const float* xbase = x + (size_t)(b*C_ + lrow) * HW_ + p0 + (cw << 5);

    float4 xst[8];
    float4 wst;
#pragma unroll
    for (int u = 0; u < 8; u++) xst[u] = *(const float4*)(xbase + (u << 2));
    wst = *(const float4*)(w1 + kw*C_ + (cq << 2));
    {
        float part = 0.f;
#pragma unroll
        for (int u = 0; u < 8; u++)
            part += xst[u].x + xst[u].y + xst[u].z + xst[u].w;
        atomicAdd(&aps[lrow], part);
    }

    for (int cc = 0; cc < 512; cc += 32) {
        __syncthreads();
#pragma unroll
        for (int j = 0; j < 8; j++) {
            int u = (j + cw) & 7;
            *(float4*)&xs[(lrow << 8) + (((cw << 3) + u) << 2)] = xst[u];
        }
        *(float4*)&ws2[(kw << 5) + (cq << 2)] = wst;
        __syncthreads();

        if (cc + 32 < 512) {
            const float* xn = xbase + (size_t)(cc + 32) * HW_;
#pragma unroll
            for (int u = 0; u < 8; u++) xst[u] = *(const float4*)(xn + (u << 2));
            wst = *(const float4*)(w1 + kw*C_ + cc + 32 + (cq << 2));
            float part = 0.f;
#pragma unroll
            for (int u = 0; u < 8; u++)
                part += xst[u].x + xst[u].y + xst[u].z + xst[u].w;
            atomicAdd(&aps[cc + 32 + lrow], part);
        }

#pragma unroll
        for (int cl = 0; cl < 32; cl++) {
            float4 xa = *(const float4*)&xs[(cl << 8) + (tp << 2)];
            float4 xb = *(const float4*)&xs[(cl << 8) + 128 + (tp << 2)];
#pragma unroll
            for (int i = 0; i < 4; i++) {
                float wv = ws2[(((tk << 2) + i) << 5) + cl];   // broadcast
                acc[i][0] = fmaf(wv, xa.x, acc[i][0]);
                acc[i][1] = fmaf(wv, xa.y, acc[i][1]);
                acc[i][2] = fmaf(wv, xa.z, acc[i][2]);
                acc[i][3] = fmaf(wv, xa.w, acc[i][3]);
                acc[i][4] = fmaf(wv, xb.x, acc[i][4]);
                acc[i][5] = fmaf(wv, xb.y, acc[i][5]);
                acc[i][6] = fmaf(wv, xb.z, acc[i][6]);
                acc[i][7] = fmaf(wv, xb.w, acc[i][7]);
            }
        }
    }

#pragma unroll
    for (int i = 0; i < 4; i++) {
        int k = (tk << 2) + i;
        float bias = __ldg(&b1[k]);
        float4 oA = make_float4(acc[i][0]+bias, acc[i][1]+bias,
                                acc[i][2]+bias, acc[i][3]+bias);
        float4 oB = make_float4(acc[i][4]+bias, acc[i][5]+bias,
                                acc[i][6]+bias, acc[i][7]+bias);
        *(float4*)&g_h1[(size_t)(b*CM_ + k) * HW_ + p0 + (tp << 2)]       = oA;
        *(float4*)&g_h1[(size_t)(b*CM_ + k) * HW_ + p0 + 128 + (tp << 2)] = oB;
    }
    __syncthreads();
    for (int i = tid; i < 512; i += 256) atomicAdd(&g_ap[b*C_ + i], aps[i]);
}

// ---------------- K2: gg = g_w @ ap (means), t1 = ap@w0.T + b0 ----------------
// warp per output, coalesced lane-strided reads + shuffle reduction.
__global__ __launch_bounds__(256) void k_ggt1(const float* __restrict__ gw,
                                              const float* __restrict__ w0,
                                              const float* __restrict__ b0) {
    int warp = (blockIdx.x << 3) + (threadIdx.x >> 5);
    int lane = threadIdx.x & 31;
    if (warp < B_*CI_) {
        int b = warp >> 6, ci = warp & 63;
        const float* ar = g_ap + b*C_;
        const float* wr = gw + ci*C_;
        float v = 0.f;
#pragma unroll
        for (int j = 0; j < 16; j++) v = fmaf(ar[lane + j*32], wr[lane + j*32], v);
#pragma unroll
        for (int o = 16; o; o >>= 1) v += __shfl_xor_sync(0xffffffffu, v, o);
        if (lane == 0) g_gg[warp] = v * INV_HW;
    } else if (warp < B_*CI_ + B_*CM_) {
        int o = warp - B_*CI_;
        int b = o >> 5, j = o & 31;
        const float* ar = g_ap + b*C_;
        const float* wr = w0 + j*C_;
        float v = 0.f;
#pragma unroll
        for (int k = 0; k < 16; k++) v = fmaf(ar[lane + k*32], wr[lane + k*32], v);
#pragma unroll
        for (int s = 16; s; s >>= 1) v += __shfl_xor_sync(0xffffffffu, v, s);
        if (lane == 0) g_t1[o] = v * INV_HW + __ldg(&b0[j]);
    }
}

// ---------------- K3: FUSED 3x3 conv (32->32) + 1x1 conv (32->512) + stats --
// grid (16 tiles of 16x16, 16 b), 512 threads.
__global__ __launch_bounds__(512) void k_conv32(const float* __restrict__ w3,
                                                const float* __restrict__ b3,
                                                const float* __restrict__ w2,
                                                const float* __restrict__ b2) {
    extern __shared__ float sm3[];
    float* w3s = sm3;            // 9216: [(ci*9+q)*32 + co]
    float* ins = sm3 + 9216;     // phase1: 32*18*18 = 10368 ; phase2: h3 [256][36]

    const int tid = threadIdx.x;
    const int b = blockIdx.y, tile = blockIdx.x;
    const int ty0 = (tile >> 2) << 4, tx0 = (tile & 3) << 4;

    for (int i = tid; i < 9216; i += 512) {
        int co = i & 31, r = i >> 5;            // r = ci*9+q
        w3s[i] = w3[co * 288 + r];
    }
    for (int i = tid; i < 10368; i += 512) {
        int ci = i / 324; int rem = i - ci*324;
        int yy = rem / 18; int xx = rem - yy*18;
        int gy = ty0 - 1 + yy, gx = tx0 - 1 + xx;
        float v = 0.f;
        if ((unsigned)gy < 64u && (unsigned)gx < 64u)
            v = g_h1[((b*CM_ + ci) << 12) + (gy << 6) + gx];
        ins[i] = v;
    }
    __syncthreads();

    // ---- phase 1: 3x3 conv ----
    const int half = tid >> 8;           // 0/1 -> co base = half*16
    const int px = tid & 255;
    const int py = px >> 4, pxx = px & 15;

    float acc[16];
#pragma unroll
    for (int i = 0; i < 16; i++) acc[i] = 0.f;

    for (int ci = 0; ci < 32; ci++) {
        const float* ib = &ins[ci*324 + py*18 + pxx];
#pragma unroll
        for (int q = 0; q < 9; q++) {
            float v = ib[(q/3)*18 + (q%3)];
            const float4* wr = (const float4*)&w3s[((ci*9 + q) << 5) + (half << 4)];
#pragma unroll
            for (int g = 0; g < 4; g++) {
                float4 wv = wr[g];
                acc[g*4+0] = fmaf(wv.x, v, acc[g*4+0]);
                acc[g*4+1] = fmaf(wv.y, v, acc[g*4+1]);
                acc[g*4+2] = fmaf(wv.z, v, acc[g*4+2]);
                acc[g*4+3] = fmaf(wv.w, v, acc[g*4+3]);
            }
        }
    }
    __syncthreads();   // everyone done reading ins before reuse

    // store h3 tile: [p][k], stride 36 (float4-aligned)
#pragma unroll
    for (int g = 0; g < 4; g++) {
        float4 o = make_float4(acc[g*4+0] + __ldg(&b3[(half<<4)+g*4+0]),
                               acc[g*4+1] + __ldg(&b3[(half<<4)+g*4+1]),
                               acc[g*4+2] + __ldg(&b3[(half<<4)+g*4+2]),
                               acc[g*4+3] + __ldg(&b3[(half<<4)+g*4+3]));
        *(float4*)&ins[px*36 + (half << 4) + (g << 2)] = o;
    }
    __syncthreads();

    // ---- phase 2: 1x1 conv 32->512 + ReLU + stats ----
    const int c = tid;
    float wr2[32];
#pragma unroll
    for (int g = 0; g < 8; g++)
        *(float4*)&wr2[g*4] = *(const float4*)&w2[(c << 5) + (g << 2)];
    const float bias = __ldg(&b2[c]);

    float s = 0.f, q = 0.f;
#pragma unroll 2
    for (int p = 0; p < 256; p++) {
        const float* row = &ins[p*36];
        float y0 = bias, y1 = 0.f;
#pragma unroll
        for (int g = 0; g < 8; g += 2) {
            float4 h0 = *(const float4*)(row + (g << 2));
            float4 h1 = *(const float4*)(row + ((g+1) << 2));
            y0 = fmaf(wr2[g*4+0], h0.x, y0); y0 = fmaf(wr2[g*4+1], h0.y, y0);
            y0 = fmaf(wr2[g*4+2], h0.z, y0); y0 = fmaf(wr2[g*4+3], h0.w, y0);
            y1 = fmaf(wr2[g*4+4], h1.x, y1); y1 = fmaf(wr2[g*4+5], h1.y, y1);
            y1 = fmaf(wr2[g*4+6], h1.z, y1); y1 = fmaf(wr2[g*4+7], h1.w, y1);
        }
        float y = fmaxf(y0 + y1, 0.f);
        s += y; q = fmaf(y, y, q);
    }
    atomicAdd(&g_sum[b*C_ + c], s);
    atomicAdd(&g_ssq[b*C_ + c], q);
}

// ---------------- K4: per-(b,c) combine -> Sum_c m[b][c] ----------------
// grid 16 (b), 512 threads (c). Reads precomputed g_t1 / g_gg.
__global__ __launch_bounds__(512) void k_combine(const float* __restrict__ aw1,
                                                 const float* __restrict__ ab1,
                                                 const float* __restrict__ ag,
                                                 const float* __restrict__ abeta,
                                                 const float* __restrict__ lg,
                                                 const float* __restrict__ lb,
                                                 const float* __restrict__ maskw) {
    __shared__ float t1s[B_*CM_];
    __shared__ float ggs[CI_];
    __shared__ float red;
    const int tid = threadIdx.x, b = blockIdx.x, c = tid;

    t1s[tid] = g_t1[tid];
    if (tid < CI_) ggs[tid] = g_gg[(b << 6) + tid];
    if (tid == 0) red = 0.f;
    __syncthreads();

    float wr[32];
#pragma unroll
    for (int g = 0; g < 8; g++)
        *(float4*)&wr[g*4] = *(const float4*)&aw1[(c << 5) + (g << 2)];
    const float bb = __ldg(&ab1[c]);

    float mu = 0.f, e2 = 0.f, vown = 0.f;
#pragma unroll
    for (int bp = 0; bp < 16; bp++) {
        float v = bb;
#pragma unroll
        for (int j = 0; j < 32; j++) v = fmaf(t1s[(bp << 5) + j], wr[j], v);
        mu += v; e2 = fmaf(v, v, e2);
        if (bp == b) vown = v;
    }
    mu *= (1.f/16.f); e2 *= (1.f/16.f);
    float var = e2 - mu*mu;
    float acv = fmaxf((vown - mu) * rsqrtf(var + EPSF) * __ldg(&ag[c]) + __ldg(&abeta[c]), 0.f);

    float ssum = 0.f, sssq = 0.f, sb = 0.f;
#pragma unroll
    for (int bp = 0; bp < 16; bp++) {
        float s = g_sum[(bp << 9) + c];
        ssum += s; sssq += g_ssq[(bp << 9) + c];
        if (bp == b) sb = s;
    }
    float muA  = ssum * (INV_HW / 16.f);
    float e2A  = sssq * (INV_HW / 16.f);
    float varA = e2A - muA*muA;
    float gals = (sb * INV_HW - muA) * rsqrtf(varA + EPSF) * __ldg(&lg[c]) + __ldg(&lb[c]);

    float gacc = g_ap[(b << 9) + c] * INV_HW;
    const float* mr = maskw + (c << 6);
#pragma unroll
    for (int qd = 0; qd < 16; qd++) {
        float4 mv = *(const float4*)&mr[qd << 2];
        gacc = fmaf(mv.x, ggs[qd*4+0], gacc);
        gacc = fmaf(mv.y, ggs[qd*4+1], gacc);
        gacc = fmaf(mv.z, ggs[qd*4+2], gacc);
        gacc = fmaf(mv.w, ggs[qd*4+3], gacc);
    }

    float m = fmaxf(fmaxf(acv, gals), gacc);
#pragma unroll
    for (int o = 16; o; o >>= 1) m += __shfl_xor_sync(0xffffffffu, m, o);
    if ((tid & 31) == 0) atomicAdd(&red, m);
    __syncthreads();
    if (tid == 0) g_red[b] = red;
}

// ---------------- K5: softmax over batch ----------------
__global__ void k_softmax() {
    int lane = threadIdx.x;
    float v = (lane < 16) ? g_red[lane] * (1.f/512.f) : -1e30f;
    float mx = v;
#pragma unroll
    for (int o = 16; o; o >>= 1) mx = fmaxf(mx, __shfl_xor_sync(0xffffffffu, mx, o));
    float e = (lane < 16) ? expf(v - mx) : 0.f;
    float s = e;
#pragma unroll
    for (int o = 16; o; o >>= 1) s += __shfl_xor_sync(0xffffffffu, s, o);
    if (lane < 16) g_sm[lane] = e / s;
}

// ---------------- K6: out = sm[b] * x ----------------
__global__ __launch_bounds__(256) void k_scale(const float4* __restrict__ x,
                                               float4* __restrict__ out) {
    __shared__ float sms[16];
    if (threadIdx.x < 16) sms[threadIdx.x] = g_sm[threadIdx.x];
    __syncthreads();
    const int n4 = B_*C_*HW_/4;   // 8388608
    for (int i = blockIdx.x * blockDim.x + threadIdx.x; i < n4;
         i += gridDim.x * blockDim.x) {
        float s = sms[i >> 19];
        float4 v = x[i];
        out[i] = make_float4(v.x*s, v.y*s, v.z*s, v.w*s);
    }
}

// ---------------- launch ----------------
extern "C" void kernel_launch(void* const* d_in, const int* in_sizes, int n_in,
                              void* d_out, int out_size) {
    const float* x        = (const float*)d_in[0];
    const float* ac_w0    = (const float*)d_in[1];
    const float* ac_b0    = (const float*)d_in[2];
    const float* ac_w1    = (const float*)d_in[3];
    const float* ac_b1    = (const float*)d_in[4];
    const float* ac_gamma = (const float*)d_in[5];
    const float* ac_beta  = (const float*)d_in[6];
    const float* als_w1   = (const float*)d_in[7];
    const float* als_b1   = (const float*)d_in[8];
    const float* als_w3   = (const float*)d_in[9];
    const float* als_b3   = (const float*)d_in[10];
    const float* als_w2   = (const float*)d_in[11];
    const float* als_b2   = (const float*)d_in[12];
    const float* als_gamma= (const float*)d_in[13];
    const float* als_beta = (const float*)d_in[14];
    // d_in[15] = phi_w, d_in[16] = theta_w : provably unused (softmax col sums = 1)
    const float* g_w      = (const float*)d_in[17];
    const float* mask_w   = (const float*)d_in[18];
    float* out = (float*)d_out;

    const int SMEM32 = (9216 + 10368) * 4;   // 78336 B
    cudaFuncSetAttribute(k_conv32, cudaFuncAttributeMaxDynamicSharedMemorySize, SMEM32);

    k_zero<<<16, 512>>>();
    k_conv1<<<dim3(16, 16), 256>>>(x, als_w1, als_b1);
    k_ggt1<<<192, 256>>>(g_w, ac_w0, ac_b0);
    k_conv32<<<dim3(16, 16), 512, SMEM32>>>(als_w3, als_b3, als_w2, als_b2);
    k_combine<<<16, 512>>>(ac_w1, ac_b1, ac_gamma, ac_beta,
                           als_gamma, als_beta, mask_w);
    k_softmax<<<1, 32>>>();
    k_scale<<<4736, 256>>>((const float4*)x, (float4*)out);
}